// round 7
// baseline (speedup 1.0000x reference)
#include <cuda_runtime.h>

#define NN 100000
#define EE 1000000
#define ET (EE + NN)          // edges + self loops
#define HC 128                // H*C
#define CC 64
#define EPS 1e-5f
#define SLOPE 0.2f
#define NB1 ((NN + 1023) / 1024)   // 98 scan blocks
#define FULL 0xffffffffu

// ---------------- scratch (device globals) ----------------
__device__ float4 g_h[NN * 32];      // h: (N, H*C) as float4[32]/node   51.2MB
__device__ float  g_as[NN * 2];      // per-node per-head attention src score
__device__ float  g_ad[NN * 2];
__device__ float  g_hm[NN * CC];     // head-mean (pre-BN affine)       25.6MB
__device__ double g_cs[3][CC], g_css[3][CC];
__device__ float  g_scale[CC], g_shift[CC];
// CSR
__device__ int    g_cnt[NN];
__device__ int    g_row[NN + 1];
__device__ int    g_cur[NN];
__device__ int    g_srt[ET];         // src ids sorted by dst
__device__ int    g_bsum[128];

__device__ __forceinline__ float lrelu(float v) { return v > 0.f ? v : SLOPE * v; }

// ==================== init: zero counters + BN stats ====================
__global__ void init_kernel() {
    int i = blockIdx.x * blockDim.x + threadIdx.x;
    if (i < NN) g_cnt[i] = 0;
    if (i < 3 * CC) { ((double*)g_cs)[i] = 0.0; ((double*)g_css)[i] = 0.0; }
}

__global__ void hist_kernel(const int* __restrict__ dst) {
    int t = blockIdx.x * blockDim.x + threadIdx.x;
    if (t >= ET) return;
    int d = (t < EE) ? dst[t] : t - EE;
    atomicAdd(&g_cnt[d], 1);
}

__global__ void scan1_kernel() {
    int i = blockIdx.x * 1024 + threadIdx.x;
    int v = (i < NN) ? g_cnt[i] : 0;
    __shared__ int sh[1024];
    sh[threadIdx.x] = v;
    __syncthreads();
    for (int o = 1; o < 1024; o <<= 1) {
        int t = (threadIdx.x >= o) ? sh[threadIdx.x - o] : 0;
        __syncthreads();
        sh[threadIdx.x] += t;
        __syncthreads();
    }
    if (i < NN) g_row[i] = sh[threadIdx.x] - v;     // exclusive
    if (threadIdx.x == 1023) g_bsum[blockIdx.x] = sh[1023];
}

__global__ void scan2_kernel() {
    int i = threadIdx.x;                            // 128 threads
    int v = (i < NB1) ? g_bsum[i] : 0;
    __shared__ int sh[128];
    sh[i] = v;
    __syncthreads();
    for (int o = 1; o < 128; o <<= 1) {
        int t = (i >= o) ? sh[i - o] : 0;
        __syncthreads();
        sh[i] += t;
        __syncthreads();
    }
    if (i < NB1) g_bsum[i] = sh[i] - v;             // exclusive
}

__global__ void scan3_kernel() {
    int i = blockIdx.x * blockDim.x + threadIdx.x;
    if (i < NN) {
        int r = g_row[i] + g_bsum[i >> 10];
        g_row[i] = r;
        g_cur[i] = r;
    }
    if (i == 0) g_row[NN] = ET;
}

__global__ void scatter_kernel(const int* __restrict__ src, const int* __restrict__ dst) {
    int t = blockIdx.x * blockDim.x + threadIdx.x;
    if (t >= ET) return;
    int s, d;
    if (t < EE) { s = src[t]; d = dst[t]; } else { s = d = t - EE; }
    int pos = atomicAdd(&g_cur[d], 1);
    g_srt[pos] = s;
}

// ==================== per-layer kernels ====================
// linear: h = in @ W, plus a_s, a_d per node/head. block=128 (one node)
__global__ void lin_kernel(const float* __restrict__ xext,
                           const float* __restrict__ W,
                           const float* __restrict__ att_s,
                           const float* __restrict__ att_d,
                           int din, int use_internal) {
    int n = blockIdx.x;
    int j = threadIdx.x;
    __shared__ float xs[64];
    __shared__ float ps[4], pd[4];
    if (j < din) {
        float v;
        if (use_internal) {
            v = g_hm[n * CC + j] * g_scale[j] + g_shift[j];
            v = v > 0.f ? v : 0.f;
        } else {
            v = xext[n * din + j];
        }
        xs[j] = v;
    }
    __syncthreads();
    float acc = 0.f;
#pragma unroll 8
    for (int k = 0; k < din; k++) acc = fmaf(xs[k], W[k * HC + j], acc);
    ((float*)g_h)[n * HC + j] = acc;
    float vs = acc * att_s[j];
    float vd = acc * att_d[j];
#pragma unroll
    for (int o = 16; o; o >>= 1) {
        vs += __shfl_down_sync(FULL, vs, o);
        vd += __shfl_down_sync(FULL, vd, o);
    }
    int w = j >> 5;
    if ((j & 31) == 0) { ps[w] = vs; pd[w] = vd; }
    __syncthreads();
    if (j == 0)  { g_as[n * 2 + 0] = ps[0] + ps[1]; g_ad[n * 2 + 0] = pd[0] + pd[1]; }
    if (j == 64) { g_as[n * 2 + 1] = ps[2] + ps[3]; g_ad[n * 2 + 1] = pd[2] + pd[3]; }
}

// fused GAT aggregation: warp per node, attention in registers, unrolled gather
__global__ void agg_kernel(const float* __restrict__ bias) {
    int node = blockIdx.x * 8 + (threadIdx.x >> 5);
    if (node >= NN) return;
    int lane = threadIdx.x & 31;
    int beg = g_row[node], end = g_row[node + 1];
    int deg = end - beg;
    float ad0 = g_ad[node * 2], ad1 = g_ad[node * 2 + 1];
    int h = lane >> 4;
    float4 acc = make_float4(0.f, 0.f, 0.f, 0.f);

    if (deg <= 32) {
        // ---- fast path: one lane per edge, attention fully in registers ----
        int s = (lane < deg) ? g_srt[beg + lane] : 0;
        float e0 = -1e30f, e1 = -1e30f;
        if (lane < deg) {
            float as0 = g_as[s * 2], as1 = g_as[s * 2 + 1];
            e0 = lrelu(as0 + ad0);
            e1 = lrelu(as1 + ad1);
        }
        float m0 = e0, m1 = e1;
#pragma unroll
        for (int o = 16; o; o >>= 1) {
            m0 = fmaxf(m0, __shfl_xor_sync(FULL, m0, o));
            m1 = fmaxf(m1, __shfl_xor_sync(FULL, m1, o));
        }
        float ee0 = (lane < deg) ? __expf(e0 - m0) : 0.f;
        float ee1 = (lane < deg) ? __expf(e1 - m1) : 0.f;
        float s0 = ee0, s1 = ee1;
#pragma unroll
        for (int o = 16; o; o >>= 1) {
            s0 += __shfl_xor_sync(FULL, s0, o);
            s1 += __shfl_xor_sync(FULL, s1, o);
        }
        float al0 = ee0 / (s0 + 1e-16f);
        float al1 = ee1 / (s1 + 1e-16f);

        int i = 0;
        for (; i + 2 <= deg; i += 2) {
            int sa = __shfl_sync(FULL, s, i);
            int sb = __shfl_sync(FULL, s, i + 1);
            float a0a = __shfl_sync(FULL, al0, i);
            float a1a = __shfl_sync(FULL, al1, i);
            float a0b = __shfl_sync(FULL, al0, i + 1);
            float a1b = __shfl_sync(FULL, al1, i + 1);
            float aa = h ? a1a : a0a;
            float ab = h ? a1b : a0b;
            float4 va = g_h[sa * 32 + lane];
            float4 vb = g_h[sb * 32 + lane];
            acc.x = fmaf(aa, va.x, fmaf(ab, vb.x, acc.x));
            acc.y = fmaf(aa, va.y, fmaf(ab, vb.y, acc.y));
            acc.z = fmaf(aa, va.z, fmaf(ab, vb.z, acc.z));
            acc.w = fmaf(aa, va.w, fmaf(ab, vb.w, acc.w));
        }
        if (i < deg) {
            int sa = __shfl_sync(FULL, s, i);
            float a0a = __shfl_sync(FULL, al0, i);
            float a1a = __shfl_sync(FULL, al1, i);
            float aa = h ? a1a : a0a;
            float4 va = g_h[sa * 32 + lane];
            acc.x = fmaf(aa, va.x, acc.x);
            acc.y = fmaf(aa, va.y, acc.y);
            acc.z = fmaf(aa, va.z, acc.z);
            acc.w = fmaf(aa, va.w, acc.w);
        }
    } else {
        // ---- general path (rare): 3-pass ----
        float m0 = -1e30f, m1 = -1e30f;
        for (int i = beg + lane; i < end; i += 32) {
            int s = g_srt[i];
            m0 = fmaxf(m0, lrelu(g_as[s * 2]     + ad0));
            m1 = fmaxf(m1, lrelu(g_as[s * 2 + 1] + ad1));
        }
#pragma unroll
        for (int o = 16; o; o >>= 1) {
            m0 = fmaxf(m0, __shfl_xor_sync(FULL, m0, o));
            m1 = fmaxf(m1, __shfl_xor_sync(FULL, m1, o));
        }
        float s0 = 0.f, s1 = 0.f;
        for (int i = beg + lane; i < end; i += 32) {
            int s = g_srt[i];
            s0 += __expf(lrelu(g_as[s * 2]     + ad0) - m0);
            s1 += __expf(lrelu(g_as[s * 2 + 1] + ad1) - m1);
        }
#pragma unroll
        for (int o = 16; o; o >>= 1) {
            s0 += __shfl_xor_sync(FULL, s0, o);
            s1 += __shfl_xor_sync(FULL, s1, o);
        }
        float mh  = h ? m1 : m0;
        float adh = h ? ad1 : ad0;
        float inv = 1.f / ((h ? s1 : s0) + 1e-16f);
        for (int i = beg; i < end; i++) {
            int s = g_srt[i];
            float a = __expf(lrelu(g_as[s * 2 + h] + adh) - mh) * inv;
            float4 hv = g_h[s * 32 + lane];
            acc.x = fmaf(a, hv.x, acc.x);
            acc.y = fmaf(a, hv.y, acc.y);
            acc.z = fmaf(a, hv.z, acc.z);
            acc.w = fmaf(a, hv.w, acc.w);
        }
    }

    // head mean: lanes 0..15 combine with lanes 16..31
    float ox = __shfl_down_sync(FULL, acc.x, 16);
    float oy = __shfl_down_sync(FULL, acc.y, 16);
    float oz = __shfl_down_sync(FULL, acc.z, 16);
    float ow = __shfl_down_sync(FULL, acc.w, 16);
    if (lane < 16) {
        const float4 b4 = ((const float4*)bias)[lane];
        float4 r;
        r.x = 0.5f * (acc.x + ox) + b4.x;
        r.y = 0.5f * (acc.y + oy) + b4.y;
        r.z = 0.5f * (acc.z + oz) + b4.z;
        r.w = 0.5f * (acc.w + ow) + b4.w;
        ((float4*)g_hm)[node * 16 + lane] = r;
    }
}

// BN stats over g_hm: 256 threads = 16 rows x 16 float4-channel-groups
__global__ void bn_stats_kernel(int layer) {
    int c4 = threadIdx.x & 15;
    int r  = threadIdx.x >> 4;
    float4 s1 = make_float4(0.f, 0.f, 0.f, 0.f);
    float4 s2 = make_float4(0.f, 0.f, 0.f, 0.f);
    for (int n = blockIdx.x * 16 + r; n < NN; n += gridDim.x * 16) {
        float4 v = ((const float4*)g_hm)[n * 16 + c4];
        s1.x += v.x; s1.y += v.y; s1.z += v.z; s1.w += v.w;
        s2.x = fmaf(v.x, v.x, s2.x); s2.y = fmaf(v.y, v.y, s2.y);
        s2.z = fmaf(v.z, v.z, s2.z); s2.w = fmaf(v.w, v.w, s2.w);
    }
    __shared__ float4 sh1[256], sh2[256];
    sh1[threadIdx.x] = s1; sh2[threadIdx.x] = s2;
    __syncthreads();
    for (int o = 8; o; o >>= 1) {
        if (r < o) {
            float4 a = sh1[threadIdx.x + o * 16], b = sh2[threadIdx.x + o * 16];
            s1.x += a.x; s1.y += a.y; s1.z += a.z; s1.w += a.w;
            s2.x += b.x; s2.y += b.y; s2.z += b.z; s2.w += b.w;
            sh1[threadIdx.x] = s1; sh2[threadIdx.x] = s2;
        }
        __syncthreads();
    }
    if (r == 0) {
        int c = c4 * 4;
        atomicAdd(&g_cs[layer][c + 0], (double)s1.x);
        atomicAdd(&g_cs[layer][c + 1], (double)s1.y);
        atomicAdd(&g_cs[layer][c + 2], (double)s1.z);
        atomicAdd(&g_cs[layer][c + 3], (double)s1.w);
        atomicAdd(&g_css[layer][c + 0], (double)s2.x);
        atomicAdd(&g_css[layer][c + 1], (double)s2.y);
        atomicAdd(&g_css[layer][c + 2], (double)s2.z);
        atomicAdd(&g_css[layer][c + 3], (double)s2.w);
    }
}

__global__ void bn_fin_kernel(const float* __restrict__ gw, const float* __restrict__ be, int layer) {
    int c = threadIdx.x;
    float m = (float)(g_cs[layer][c] / (double)NN);
    float var = (float)(g_css[layer][c] / (double)NN) - m * m;
    var = fmaxf(var, 0.f);
    float rs = rsqrtf(var + EPS);
    float sc = rs * gw[c];
    g_scale[c] = sc;
    g_shift[c] = be[c] - m * sc;
}

// ==================== MLP heads ====================
__global__ void mlp_kernel(const float* __restrict__ x0,
                           const float* __restrict__ mW1, const float* __restrict__ mb1,
                           const float* __restrict__ mW2, const float* __restrict__ mb2,
                           const float* __restrict__ pW, const float* __restrict__ pb,
                           const float* __restrict__ vW, const float* __restrict__ vb,
                           float* __restrict__ out) {
    int n = blockIdx.x;
    int j = threadIdx.x;
    __shared__ float hc[72];
    __shared__ float h1[64];
    __shared__ float pl[2], pv[2];
    {
        float v = g_hm[n * CC + j] * g_scale[j] + g_shift[j];
        hc[j] = v > 0.f ? v : 0.f;
    }
    if (j < 5) hc[64 + j] = x0[n * 16 + 9 + j];
    __syncthreads();
    float a = mb1[j];
#pragma unroll
    for (int k = 0; k < 69; k++) a = fmaf(hc[k], mW1[k * 64 + j], a);
    a = a > 0.f ? a : 0.f;
    h1[j] = a;
    __syncthreads();
    float b = mb2[j];
#pragma unroll
    for (int k = 0; k < 64; k++) b = fmaf(h1[k], mW2[k * 64 + j], b);
    float lg = b * pW[j];
    float vl = b * vW[j];
#pragma unroll
    for (int o = 16; o; o >>= 1) {
        lg += __shfl_down_sync(FULL, lg, o);
        vl += __shfl_down_sync(FULL, vl, o);
    }
    int w = j >> 5;
    if ((j & 31) == 0) { pl[w] = lg; pv[w] = vl; }
    __syncthreads();
    if (j == 0) {
        out[n]      = pl[0] + pl[1] + pb[0];
        out[NN + n] = pv[0] + pv[1] + vb[0];
    }
}

// ==================== launch ====================
extern "C" void kernel_launch(void* const* d_in, const int* in_sizes, int n_in,
                              void* d_out, int out_size) {
    const float* x   = (const float*)d_in[0];
    const int*   ei  = (const int*)d_in[1];
    const int*   src = ei;
    const int*   dst = ei + EE;
    float* out = (float*)d_out;

    // ---- CSR build ----
    init_kernel<<<(NN + 255) / 256, 256>>>();
    int eb = (ET + 255) / 256;
    hist_kernel<<<eb, 256>>>(dst);
    scan1_kernel<<<NB1, 1024>>>();
    scan2_kernel<<<1, 128>>>();
    scan3_kernel<<<(NN + 255) / 256, 256>>>();
    scatter_kernel<<<eb, 256>>>(src, dst);

    const int base[3] = {2, 8, 14};
    const int din[3]  = {16, 64, 64};

    for (int l = 0; l < 3; l++) {
        const float* W   = (const float*)d_in[base[l] + 0];
        const float* as_ = (const float*)d_in[base[l] + 1];
        const float* ad_ = (const float*)d_in[base[l] + 2];
        const float* b_  = (const float*)d_in[base[l] + 3];
        const float* g_  = (const float*)d_in[base[l] + 4];
        const float* be_ = (const float*)d_in[base[l] + 5];

        lin_kernel<<<NN, 128>>>(x, W, as_, ad_, din[l], l > 0 ? 1 : 0);
        agg_kernel<<<(NN + 7) / 8, 256>>>(b_);
        bn_stats_kernel<<<296, 256>>>(l);
        bn_fin_kernel<<<1, 64>>>(g_, be_, l);
    }

    const float* mW1 = (const float*)d_in[20];
    const float* mb1 = (const float*)d_in[21];
    const float* mW2 = (const float*)d_in[22];
    const float* mb2 = (const float*)d_in[23];
    const float* pW  = (const float*)d_in[24];
    const float* pb  = (const float*)d_in[25];
    const float* vW  = (const float*)d_in[26];
    const float* vb  = (const float*)d_in[27];
    mlp_kernel<<<NN, 64>>>(x, mW1, mb1, mW2, mb2, pW, pb, vW, vb, out);
}

// round 11
// speedup vs baseline: 1.3473x; 1.3473x over previous
#include <cuda_runtime.h>

#define NN 100000
#define EE 1000000
#define ET (EE + NN)          // edges + self loops
#define HC 128                // H*C
#define CC 64
#define EPS 1e-5f
#define SLOPE 0.2f
#define NB1 ((NN + 1023) / 1024)   // 98 scan blocks
#define FULL 0xffffffffu

// ---------------- scratch (device globals) ----------------
__device__ float4 g_h[NN * 32];      // h: (N, H*C) as float4[32]/node   51.2MB
__device__ float  g_as[NN * 2];      // per-node per-head attention src score
__device__ float  g_ad[NN * 2];
__device__ float  g_hm[NN * CC];     // head-mean (pre-BN affine)       25.6MB
__device__ double g_cs[3][CC], g_css[3][CC];
__device__ float  g_scale[CC], g_shift[CC];
__device__ int    g_done;
// CSR
__device__ int    g_cnt[NN];
__device__ int    g_row[NN + 1];
__device__ int    g_cur[NN];
__device__ int    g_srt[ET];         // src ids sorted by dst
__device__ int    g_bsum[128];

__device__ __forceinline__ float lrelu(float v) { return v > 0.f ? v : SLOPE * v; }

// ==================== init: zero counters + BN stats ====================
__global__ void init_kernel() {
    int i = blockIdx.x * blockDim.x + threadIdx.x;
    if (i < NN) g_cnt[i] = 0;
    if (i < 3 * CC) { ((double*)g_cs)[i] = 0.0; ((double*)g_css)[i] = 0.0; }
    if (i == 0) g_done = 0;
}

__global__ void hist_kernel(const int* __restrict__ dst) {
    int t = blockIdx.x * blockDim.x + threadIdx.x;
    if (t >= ET) return;
    int d = (t < EE) ? dst[t] : t - EE;
    atomicAdd(&g_cnt[d], 1);
}

// warp-shuffle 3-level scan, 1024 threads
__global__ void scan1_kernel() {
    int i = blockIdx.x * 1024 + threadIdx.x;
    int v = (i < NN) ? g_cnt[i] : 0;
    int lane = threadIdx.x & 31, warp = threadIdx.x >> 5;
    int s = v;
#pragma unroll
    for (int o = 1; o < 32; o <<= 1) {
        int t = __shfl_up_sync(FULL, s, o);
        if (lane >= o) s += t;
    }
    __shared__ int wsum[32];
    if (lane == 31) wsum[warp] = s;
    __syncthreads();
    if (warp == 0) {
        int w = wsum[lane];
#pragma unroll
        for (int o = 1; o < 32; o <<= 1) {
            int t = __shfl_up_sync(FULL, w, o);
            if (lane >= o) w += t;
        }
        wsum[lane] = w;
    }
    __syncthreads();
    int incl = s + (warp ? wsum[warp - 1] : 0);
    if (i < NN) g_row[i] = incl - v;                // exclusive
    if (threadIdx.x == 1023) g_bsum[blockIdx.x] = incl;
}

__global__ void scan2_kernel() {
    int i = threadIdx.x;                            // 128 threads
    int v = (i < NB1) ? g_bsum[i] : 0;
    int lane = i & 31, warp = i >> 5;
    int s = v;
#pragma unroll
    for (int o = 1; o < 32; o <<= 1) {
        int t = __shfl_up_sync(FULL, s, o);
        if (lane >= o) s += t;
    }
    __shared__ int wsum[4];
    if (lane == 31) wsum[warp] = s;
    __syncthreads();
    int base = 0;
    for (int w = 0; w < warp; w++) base += wsum[w];
    if (i < NB1) g_bsum[i] = s + base - v;          // exclusive
}

__global__ void scan3_kernel() {
    int i = blockIdx.x * blockDim.x + threadIdx.x;
    if (i < NN) {
        int r = g_row[i] + g_bsum[i >> 10];
        g_row[i] = r;
        g_cur[i] = r;
    }
    if (i == 0) g_row[NN] = ET;
}

__global__ void scatter_kernel(const int* __restrict__ src, const int* __restrict__ dst) {
    int t = blockIdx.x * blockDim.x + threadIdx.x;
    if (t >= ET) return;
    int s, d;
    if (t < EE) { s = src[t]; d = dst[t]; } else { s = d = t - EE; }
    int pos = atomicAdd(&g_cur[d], 1);
    g_srt[pos] = s;
}

// ==================== lin v2: W in registers, node tiles through smem ====================
// block = 128 threads; thread j owns output column j; tile = 8 nodes
template<int DIN, bool INTERNAL>
__global__ void __launch_bounds__(128) lin2_kernel(const float* __restrict__ xext,
                                                   const float* __restrict__ W,
                                                   const float* __restrict__ att_s,
                                                   const float* __restrict__ att_d) {
    int j = threadIdx.x;
    int warp = j >> 5, lane = j & 31;
    float wreg[DIN];
#pragma unroll
    for (int k = 0; k < DIN; k++) wreg[k] = W[k * HC + j];
    float asj = att_s[j], adj = att_d[j];

    __shared__ __align__(16) float xs[8][DIN];
    __shared__ float red[4][8][2];

    const int NT = (NN + 7) / 8;
    for (int tile = blockIdx.x; tile < NT; tile += gridDim.x) {
        int nbase = tile * 8;
        // cooperative load of 8 node rows
        if constexpr (INTERNAL) {
            int n = j >> 4, k4 = j & 15;
            float4 v = ((const float4*)g_hm)[(nbase + n) * 16 + k4];
            float4 sc = ((const float4*)g_scale)[k4];
            float4 sh = ((const float4*)g_shift)[k4];
            v.x = fmaxf(fmaf(v.x, sc.x, sh.x), 0.f);
            v.y = fmaxf(fmaf(v.y, sc.y, sh.y), 0.f);
            v.z = fmaxf(fmaf(v.z, sc.z, sh.z), 0.f);
            v.w = fmaxf(fmaf(v.w, sc.w, sh.w), 0.f);
            ((float4*)xs[n])[k4] = v;
        } else {
            int n = j >> 4, k = j & 15;
            xs[n][k] = xext[(nbase + n) * 16 + k];
        }
        __syncthreads();

        float acc[8];
#pragma unroll
        for (int n = 0; n < 8; n++) acc[n] = 0.f;
#pragma unroll
        for (int k4 = 0; k4 < DIN / 4; k4++) {
#pragma unroll
            for (int n = 0; n < 8; n++) {
                float4 xv = ((const float4*)xs[n])[k4];
                acc[n] = fmaf(xv.x, wreg[k4 * 4 + 0], acc[n]);
                acc[n] = fmaf(xv.y, wreg[k4 * 4 + 1], acc[n]);
                acc[n] = fmaf(xv.z, wreg[k4 * 4 + 2], acc[n]);
                acc[n] = fmaf(xv.w, wreg[k4 * 4 + 3], acc[n]);
            }
        }
        // store h + attention partials
#pragma unroll
        for (int n = 0; n < 8; n++) {
            ((float*)g_h)[(nbase + n) * HC + j] = acc[n];
            float vs = acc[n] * asj, vd = acc[n] * adj;
#pragma unroll
            for (int o = 16; o; o >>= 1) {
                vs += __shfl_down_sync(FULL, vs, o);
                vd += __shfl_down_sync(FULL, vd, o);
            }
            if (lane == 0) { red[warp][n][0] = vs; red[warp][n][1] = vd; }
        }
        __syncthreads();
        if (j < 32) {
            int n = j >> 2, h = (j >> 1) & 1, sd = j & 1;
            float v = red[h * 2][n][sd] + red[h * 2 + 1][n][sd];
            int node = nbase + n;
            if (sd == 0) g_as[node * 2 + h] = v;
            else         g_ad[node * 2 + h] = v;
        }
        __syncthreads();
    }
}

// ==================== fused GAT aggregation (unchanged, verified) ====================
__global__ void agg_kernel(const float* __restrict__ bias) {
    int node = blockIdx.x * 8 + (threadIdx.x >> 5);
    if (node >= NN) return;
    int lane = threadIdx.x & 31;
    int beg = g_row[node], end = g_row[node + 1];
    int deg = end - beg;
    float ad0 = g_ad[node * 2], ad1 = g_ad[node * 2 + 1];
    int h = lane >> 4;
    float4 acc = make_float4(0.f, 0.f, 0.f, 0.f);

    if (deg <= 32) {
        int s = (lane < deg) ? g_srt[beg + lane] : 0;
        float e0 = -1e30f, e1 = -1e30f;
        if (lane < deg) {
            float as0 = g_as[s * 2], as1 = g_as[s * 2 + 1];
            e0 = lrelu(as0 + ad0);
            e1 = lrelu(as1 + ad1);
        }
        float m0 = e0, m1 = e1;
#pragma unroll
        for (int o = 16; o; o >>= 1) {
            m0 = fmaxf(m0, __shfl_xor_sync(FULL, m0, o));
            m1 = fmaxf(m1, __shfl_xor_sync(FULL, m1, o));
        }
        float ee0 = (lane < deg) ? __expf(e0 - m0) : 0.f;
        float ee1 = (lane < deg) ? __expf(e1 - m1) : 0.f;
        float s0 = ee0, s1 = ee1;
#pragma unroll
        for (int o = 16; o; o >>= 1) {
            s0 += __shfl_xor_sync(FULL, s0, o);
            s1 += __shfl_xor_sync(FULL, s1, o);
        }
        float al0 = ee0 / (s0 + 1e-16f);
        float al1 = ee1 / (s1 + 1e-16f);

        int i = 0;
        for (; i + 2 <= deg; i += 2) {
            int sa = __shfl_sync(FULL, s, i);
            int sb = __shfl_sync(FULL, s, i + 1);
            float a0a = __shfl_sync(FULL, al0, i);
            float a1a = __shfl_sync(FULL, al1, i);
            float a0b = __shfl_sync(FULL, al0, i + 1);
            float a1b = __shfl_sync(FULL, al1, i + 1);
            float aa = h ? a1a : a0a;
            float ab = h ? a1b : a0b;
            float4 va = g_h[sa * 32 + lane];
            float4 vb = g_h[sb * 32 + lane];
            acc.x = fmaf(aa, va.x, fmaf(ab, vb.x, acc.x));
            acc.y = fmaf(aa, va.y, fmaf(ab, vb.y, acc.y));
            acc.z = fmaf(aa, va.z, fmaf(ab, vb.z, acc.z));
            acc.w = fmaf(aa, va.w, fmaf(ab, vb.w, acc.w));
        }
        if (i < deg) {
            int sa = __shfl_sync(FULL, s, i);
            float a0a = __shfl_sync(FULL, al0, i);
            float a1a = __shfl_sync(FULL, al1, i);
            float aa = h ? a1a : a0a;
            float4 va = g_h[sa * 32 + lane];
            acc.x = fmaf(aa, va.x, acc.x);
            acc.y = fmaf(aa, va.y, acc.y);
            acc.z = fmaf(aa, va.z, acc.z);
            acc.w = fmaf(aa, va.w, acc.w);
        }
    } else {
        float m0 = -1e30f, m1 = -1e30f;
        for (int i = beg + lane; i < end; i += 32) {
            int s = g_srt[i];
            m0 = fmaxf(m0, lrelu(g_as[s * 2]     + ad0));
            m1 = fmaxf(m1, lrelu(g_as[s * 2 + 1] + ad1));
        }
#pragma unroll
        for (int o = 16; o; o >>= 1) {
            m0 = fmaxf(m0, __shfl_xor_sync(FULL, m0, o));
            m1 = fmaxf(m1, __shfl_xor_sync(FULL, m1, o));
        }
        float s0 = 0.f, s1 = 0.f;
        for (int i = beg + lane; i < end; i += 32) {
            int s = g_srt[i];
            s0 += __expf(lrelu(g_as[s * 2]     + ad0) - m0);
            s1 += __expf(lrelu(g_as[s * 2 + 1] + ad1) - m1);
        }
#pragma unroll
        for (int o = 16; o; o >>= 1) {
            s0 += __shfl_xor_sync(FULL, s0, o);
            s1 += __shfl_xor_sync(FULL, s1, o);
        }
        float mh  = h ? m1 : m0;
        float adh = h ? ad1 : ad0;
        float inv = 1.f / ((h ? s1 : s0) + 1e-16f);
        for (int i = beg; i < end; i++) {
            int s = g_srt[i];
            float a = __expf(lrelu(g_as[s * 2 + h] + adh) - mh) * inv;
            float4 hv = g_h[s * 32 + lane];
            acc.x = fmaf(a, hv.x, acc.x);
            acc.y = fmaf(a, hv.y, acc.y);
            acc.z = fmaf(a, hv.z, acc.z);
            acc.w = fmaf(a, hv.w, acc.w);
        }
    }

    float ox = __shfl_down_sync(FULL, acc.x, 16);
    float oy = __shfl_down_sync(FULL, acc.y, 16);
    float oz = __shfl_down_sync(FULL, acc.z, 16);
    float ow = __shfl_down_sync(FULL, acc.w, 16);
    if (lane < 16) {
        const float4 b4 = ((const float4*)bias)[lane];
        float4 r;
        r.x = 0.5f * (acc.x + ox) + b4.x;
        r.y = 0.5f * (acc.y + oy) + b4.y;
        r.z = 0.5f * (acc.z + oz) + b4.z;
        r.w = 0.5f * (acc.w + ow) + b4.w;
        ((float4*)g_hm)[node * 16 + lane] = r;
    }
}

// ==================== BN stats + fused finalize (last-block) ====================
__global__ void bn_stats_kernel(const float* __restrict__ gw, const float* __restrict__ be, int layer) {
    int c4 = threadIdx.x & 15;
    int r  = threadIdx.x >> 4;
    float4 s1 = make_float4(0.f, 0.f, 0.f, 0.f);
    float4 s2 = make_float4(0.f, 0.f, 0.f, 0.f);
    for (int n = blockIdx.x * 16 + r; n < NN; n += gridDim.x * 16) {
        float4 v = ((const float4*)g_hm)[n * 16 + c4];
        s1.x += v.x; s1.y += v.y; s1.z += v.z; s1.w += v.w;
        s2.x = fmaf(v.x, v.x, s2.x); s2.y = fmaf(v.y, v.y, s2.y);
        s2.z = fmaf(v.z, v.z, s2.z); s2.w = fmaf(v.w, v.w, s2.w);
    }
    __shared__ float4 sh1[256], sh2[256];
    sh1[threadIdx.x] = s1; sh2[threadIdx.x] = s2;
    __syncthreads();
    for (int o = 8; o; o >>= 1) {
        if (r < o) {
            float4 a = sh1[threadIdx.x + o * 16], b = sh2[threadIdx.x + o * 16];
            s1.x += a.x; s1.y += a.y; s1.z += a.z; s1.w += a.w;
            s2.x += b.x; s2.y += b.y; s2.z += b.z; s2.w += b.w;
            sh1[threadIdx.x] = s1; sh2[threadIdx.x] = s2;
        }
        __syncthreads();
    }
    if (r == 0) {
        int c = c4 * 4;
        atomicAdd(&g_cs[layer][c + 0], (double)s1.x);
        atomicAdd(&g_cs[layer][c + 1], (double)s1.y);
        atomicAdd(&g_cs[layer][c + 2], (double)s1.z);
        atomicAdd(&g_cs[layer][c + 3], (double)s1.w);
        atomicAdd(&g_css[layer][c + 0], (double)s2.x);
        atomicAdd(&g_css[layer][c + 1], (double)s2.y);
        atomicAdd(&g_css[layer][c + 2], (double)s2.z);
        atomicAdd(&g_css[layer][c + 3], (double)s2.w);
        __threadfence();
    }
    __syncthreads();
    __shared__ int lastf;
    if (threadIdx.x == 0) lastf = (atomicAdd(&g_done, 1) == (int)gridDim.x - 1) ? 1 : 0;
    __syncthreads();
    if (lastf) {
        if (threadIdx.x == 0) g_done = 0;
        if (threadIdx.x < CC) {
            int c = threadIdx.x;
            float m = (float)(g_cs[layer][c] / (double)NN);
            float var = (float)(g_css[layer][c] / (double)NN) - m * m;
            var = fmaxf(var, 0.f);
            float sc = rsqrtf(var + EPS) * gw[c];
            g_scale[c] = sc;
            g_shift[c] = be[c] - m * sc;
        }
    }
}

// ==================== MLP v2: one node per thread, smem weights broadcast ====================
__global__ void __launch_bounds__(128) mlp2_kernel(const float* __restrict__ x0,
                           const float* __restrict__ mW1, const float* __restrict__ mb1,
                           const float* __restrict__ mW2, const float* __restrict__ mb2,
                           const float* __restrict__ pW, const float* __restrict__ pb,
                           const float* __restrict__ vW, const float* __restrict__ vb,
                           float* __restrict__ out) {
    __shared__ __align__(16) float m1t[64][72];   // m1t[j][k] = mW1[k*64+j], k<69, pad 0
    __shared__ __align__(16) float m2t[64][64];   // m2t[j][k] = mW2[k*64+j]
    __shared__ float mb1s[64], mb2s[64], pWs[64], vWs[64];
    int tid = threadIdx.x;
    for (int i = tid; i < 64 * 72; i += 128) ((float*)m1t)[i] = 0.f;
    __syncthreads();
    for (int i = tid; i < 69 * 64; i += 128) { int k = i >> 6, j = i & 63; m1t[j][k] = mW1[i]; }
    for (int i = tid; i < 64 * 64; i += 128) { int k = i >> 6, j = i & 63; m2t[j][k] = mW2[i]; }
    if (tid < 64) { mb1s[tid] = mb1[tid]; mb2s[tid] = mb2[tid]; pWs[tid] = pW[tid]; vWs[tid] = vW[tid]; }
    __syncthreads();

    int n = blockIdx.x * 128 + tid;
    if (n >= NN) return;

    float4 hc4[18];
#pragma unroll
    for (int k4 = 0; k4 < 16; k4++) {
        float4 v = ((const float4*)g_hm)[n * 16 + k4];
        float4 sc = ((const float4*)g_scale)[k4];
        float4 sh = ((const float4*)g_shift)[k4];
        v.x = fmaxf(fmaf(v.x, sc.x, sh.x), 0.f);
        v.y = fmaxf(fmaf(v.y, sc.y, sh.y), 0.f);
        v.z = fmaxf(fmaf(v.z, sc.z, sh.z), 0.f);
        v.w = fmaxf(fmaf(v.w, sc.w, sh.w), 0.f);
        hc4[k4] = v;
    }
    hc4[16] = make_float4(x0[n * 16 + 9], x0[n * 16 + 10], x0[n * 16 + 11], x0[n * 16 + 12]);
    hc4[17] = make_float4(x0[n * 16 + 13], 0.f, 0.f, 0.f);

    float h1[64];
#pragma unroll
    for (int j = 0; j < 64; j++) {
        float a = mb1s[j];
#pragma unroll
        for (int k4 = 0; k4 < 18; k4++) {
            float4 w = ((const float4*)m1t[j])[k4];
            a = fmaf(hc4[k4].x, w.x, a);
            a = fmaf(hc4[k4].y, w.y, a);
            a = fmaf(hc4[k4].z, w.z, a);
            a = fmaf(hc4[k4].w, w.w, a);
        }
        h1[j] = fmaxf(a, 0.f);
    }
    float lg = 0.f, vl = 0.f;
#pragma unroll
    for (int j = 0; j < 64; j++) {
        float b = mb2s[j];
#pragma unroll
        for (int k4 = 0; k4 < 16; k4++) {
            float4 w = ((const float4*)m2t[j])[k4];
            b = fmaf(h1[k4 * 4 + 0], w.x, b);
            b = fmaf(h1[k4 * 4 + 1], w.y, b);
            b = fmaf(h1[k4 * 4 + 2], w.z, b);
            b = fmaf(h1[k4 * 4 + 3], w.w, b);
        }
        lg = fmaf(b, pWs[j], lg);
        vl = fmaf(b, vWs[j], vl);
    }
    out[n]      = lg + pb[0];
    out[NN + n] = vl + vb[0];
}

// ==================== launch ====================
extern "C" void kernel_launch(void* const* d_in, const int* in_sizes, int n_in,
                              void* d_out, int out_size) {
    const float* x   = (const float*)d_in[0];
    const int*   ei  = (const int*)d_in[1];
    const int*   src = ei;
    const int*   dst = ei + EE;
    float* out = (float*)d_out;

    // ---- CSR build ----
    init_kernel<<<(NN + 255) / 256, 256>>>();
    int eb = (ET + 255) / 256;
    hist_kernel<<<eb, 256>>>(dst);
    scan1_kernel<<<NB1, 1024>>>();
    scan2_kernel<<<1, 128>>>();
    scan3_kernel<<<(NN + 255) / 256, 256>>>();
    scatter_kernel<<<eb, 256>>>(src, dst);

    const int base[3] = {2, 8, 14};

    for (int l = 0; l < 3; l++) {
        const float* W   = (const float*)d_in[base[l] + 0];
        const float* as_ = (const float*)d_in[base[l] + 1];
        const float* ad_ = (const float*)d_in[base[l] + 2];
        const float* b_  = (const float*)d_in[base[l] + 3];
        const float* g_  = (const float*)d_in[base[l] + 4];
        const float* be_ = (const float*)d_in[base[l] + 5];

        if (l == 0) lin2_kernel<16, false><<<1184, 128>>>(x, W, as_, ad_);
        else        lin2_kernel<64, true ><<<1184, 128>>>(x, W, as_, ad_);
        agg_kernel<<<(NN + 7) / 8, 256>>>(b_);
        bn_stats_kernel<<<296, 256>>>(g_, be_, l);
    }

    const float* mW1 = (const float*)d_in[20];
    const float* mb1 = (const float*)d_in[21];
    const float* mW2 = (const float*)d_in[22];
    const float* mb2 = (const float*)d_in[23];
    const float* pW  = (const float*)d_in[24];
    const float* pb  = (const float*)d_in[25];
    const float* vW  = (const float*)d_in[26];
    const float* vb  = (const float*)d_in[27];
    mlp2_kernel<<<(NN + 127) / 128, 128>>>(x, mW1, mb1, mW2, mb2, pW, pb, vW, vb, out);
}

// round 15
// speedup vs baseline: 1.4836x; 1.1011x over previous
#include <cuda_runtime.h>
#include <cuda_fp16.h>

#define NN 100000
#define EE 1000000
#define ET (EE + NN)          // edges + self loops
#define HC 128                // H*C
#define CC 64
#define EPS 1e-5f
#define SLOPE 0.2f
#define NB1 ((NN + 1023) / 1024)   // 98 scan blocks
#define FULL 0xffffffffu

// ---------------- scratch (device globals) ----------------
__device__ __align__(16) __half2 g_h[NN * 64];  // h: (N,128) fp16   25.6MB
__device__ float  g_as[NN * 2];      // per-node per-head attention src score
__device__ float  g_ad[NN * 2];
__device__ float  g_hm[NN * CC];     // head-mean (pre-BN affine)       25.6MB
__device__ double g_cs[3][CC], g_css[3][CC];
__device__ float  g_scale[CC], g_shift[CC];
__device__ int    g_done;
// CSR
__device__ int    g_cnt[NN];
__device__ int    g_row[NN + 1];
__device__ int    g_cur[NN];
__device__ int    g_srt[ET];         // src ids sorted by dst
__device__ int    g_bsum[128];

__device__ __forceinline__ float lrelu(float v) { return v > 0.f ? v : SLOPE * v; }

// ==================== init: zero counters + BN stats ====================
__global__ void init_kernel() {
    int i = blockIdx.x * blockDim.x + threadIdx.x;
    if (i < NN) g_cnt[i] = 0;
    if (i < 3 * CC) { ((double*)g_cs)[i] = 0.0; ((double*)g_css)[i] = 0.0; }
    if (i == 0) g_done = 0;
}

__global__ void hist_kernel(const int* __restrict__ dst) {
    int t = blockIdx.x * blockDim.x + threadIdx.x;
    if (t >= ET) return;
    int d = (t < EE) ? dst[t] : t - EE;
    atomicAdd(&g_cnt[d], 1);
}

// warp-shuffle 3-level scan, 1024 threads
__global__ void scan1_kernel() {
    int i = blockIdx.x * 1024 + threadIdx.x;
    int v = (i < NN) ? g_cnt[i] : 0;
    int lane = threadIdx.x & 31, warp = threadIdx.x >> 5;
    int s = v;
#pragma unroll
    for (int o = 1; o < 32; o <<= 1) {
        int t = __shfl_up_sync(FULL, s, o);
        if (lane >= o) s += t;
    }
    __shared__ int wsum[32];
    if (lane == 31) wsum[warp] = s;
    __syncthreads();
    if (warp == 0) {
        int w = wsum[lane];
#pragma unroll
        for (int o = 1; o < 32; o <<= 1) {
            int t = __shfl_up_sync(FULL, w, o);
            if (lane >= o) w += t;
        }
        wsum[lane] = w;
    }
    __syncthreads();
    int incl = s + (warp ? wsum[warp - 1] : 0);
    if (i < NN) g_row[i] = incl - v;                // exclusive
    if (threadIdx.x == 1023) g_bsum[blockIdx.x] = incl;
}

__global__ void scan2_kernel() {
    int i = threadIdx.x;                            // 128 threads
    int v = (i < NB1) ? g_bsum[i] : 0;
    int lane = i & 31, warp = i >> 5;
    int s = v;
#pragma unroll
    for (int o = 1; o < 32; o <<= 1) {
        int t = __shfl_up_sync(FULL, s, o);
        if (lane >= o) s += t;
    }
    __shared__ int wsum[4];
    if (lane == 31) wsum[warp] = s;
    __syncthreads();
    int base = 0;
    for (int w = 0; w < warp; w++) base += wsum[w];
    if (i < NB1) g_bsum[i] = s + base - v;          // exclusive
}

__global__ void scan3_kernel() {
    int i = blockIdx.x * blockDim.x + threadIdx.x;
    if (i < NN) {
        int r = g_row[i] + g_bsum[i >> 10];
        g_row[i] = r;
        g_cur[i] = r;
    }
    if (i == 0) g_row[NN] = ET;
}

__global__ void scatter_kernel(const int* __restrict__ src, const int* __restrict__ dst) {
    int t = blockIdx.x * blockDim.x + threadIdx.x;
    if (t >= ET) return;
    int s, d;
    if (t < EE) { s = src[t]; d = dst[t]; } else { s = d = t - EE; }
    int pos = atomicAdd(&g_cur[d], 1);
    g_srt[pos] = s;
}

// ==================== lin v2: W in registers, node tiles through smem ====================
// block = 128 threads; thread j owns output column j; tile = 8 nodes
template<int DIN, bool INTERNAL>
__global__ void __launch_bounds__(128) lin2_kernel(const float* __restrict__ xext,
                                                   const float* __restrict__ W,
                                                   const float* __restrict__ att_s,
                                                   const float* __restrict__ att_d) {
    int j = threadIdx.x;
    int warp = j >> 5, lane = j & 31;
    float wreg[DIN];
#pragma unroll
    for (int k = 0; k < DIN; k++) wreg[k] = W[k * HC + j];
    float asj = att_s[j], adj = att_d[j];

    __shared__ __align__(16) float xs[8][DIN];
    __shared__ float red[4][8][2];

    const int NT = (NN + 7) / 8;
    for (int tile = blockIdx.x; tile < NT; tile += gridDim.x) {
        int nbase = tile * 8;
        // cooperative load of 8 node rows
        if constexpr (INTERNAL) {
            int n = j >> 4, k4 = j & 15;
            float4 v = ((const float4*)g_hm)[(nbase + n) * 16 + k4];
            float4 sc = ((const float4*)g_scale)[k4];
            float4 sh = ((const float4*)g_shift)[k4];
            v.x = fmaxf(fmaf(v.x, sc.x, sh.x), 0.f);
            v.y = fmaxf(fmaf(v.y, sc.y, sh.y), 0.f);
            v.z = fmaxf(fmaf(v.z, sc.z, sh.z), 0.f);
            v.w = fmaxf(fmaf(v.w, sc.w, sh.w), 0.f);
            ((float4*)xs[n])[k4] = v;
        } else {
            int n = j >> 4, k = j & 15;
            xs[n][k] = xext[(nbase + n) * 16 + k];
        }
        __syncthreads();

        float acc[8];
#pragma unroll
        for (int n = 0; n < 8; n++) acc[n] = 0.f;
#pragma unroll
        for (int k4 = 0; k4 < DIN / 4; k4++) {
#pragma unroll
            for (int n = 0; n < 8; n++) {
                float4 xv = ((const float4*)xs[n])[k4];
                acc[n] = fmaf(xv.x, wreg[k4 * 4 + 0], acc[n]);
                acc[n] = fmaf(xv.y, wreg[k4 * 4 + 1], acc[n]);
                acc[n] = fmaf(xv.z, wreg[k4 * 4 + 2], acc[n]);
                acc[n] = fmaf(xv.w, wreg[k4 * 4 + 3], acc[n]);
            }
        }
        // store h (fp16 pair stores) + attention partials
#pragma unroll
        for (int n = 0; n < 8; n++) {
            float nb = __shfl_down_sync(FULL, acc[n], 1);
            if ((j & 1) == 0)
                g_h[(nbase + n) * 64 + (j >> 1)] = __floats2half2_rn(acc[n], nb);
            float vs = acc[n] * asj, vd = acc[n] * adj;
#pragma unroll
            for (int o = 16; o; o >>= 1) {
                vs += __shfl_down_sync(FULL, vs, o);
                vd += __shfl_down_sync(FULL, vd, o);
            }
            if (lane == 0) { red[warp][n][0] = vs; red[warp][n][1] = vd; }
        }
        __syncthreads();
        if (j < 32) {
            int n = j >> 2, h = (j >> 1) & 1, sd = j & 1;
            float v = red[h * 2][n][sd] + red[h * 2 + 1][n][sd];
            int node = nbase + n;
            if (sd == 0) g_as[node * 2 + h] = v;
            else         g_ad[node * 2 + h] = v;
        }
        __syncthreads();
    }
}

// helper: load lane's 4 channels of node s as float4
__device__ __forceinline__ float4 load_h4(int s, int lane) {
    uint2 raw = ((const uint2*)g_h)[s * 32 + lane];
    __half2 p0 = *(__half2*)&raw.x;
    __half2 p1 = *(__half2*)&raw.y;
    float2 f0 = __half22float2(p0);
    float2 f1 = __half22float2(p1);
    return make_float4(f0.x, f0.y, f1.x, f1.y);
}

// ==================== fused GAT aggregation ====================
__global__ void agg_kernel(const float* __restrict__ bias) {
    int node = blockIdx.x * 8 + (threadIdx.x >> 5);
    if (node >= NN) return;
    int lane = threadIdx.x & 31;
    int beg = g_row[node], end = g_row[node + 1];
    int deg = end - beg;
    float ad0 = g_ad[node * 2], ad1 = g_ad[node * 2 + 1];
    int h = lane >> 4;
    float4 acc = make_float4(0.f, 0.f, 0.f, 0.f);

    if (deg <= 32) {
        int s = (lane < deg) ? g_srt[beg + lane] : 0;
        float e0 = -1e30f, e1 = -1e30f;
        if (lane < deg) {
            float as0 = g_as[s * 2], as1 = g_as[s * 2 + 1];
            e0 = lrelu(as0 + ad0);
            e1 = lrelu(as1 + ad1);
        }
        float m0 = e0, m1 = e1;
#pragma unroll
        for (int o = 16; o; o >>= 1) {
            m0 = fmaxf(m0, __shfl_xor_sync(FULL, m0, o));
            m1 = fmaxf(m1, __shfl_xor_sync(FULL, m1, o));
        }
        float ee0 = (lane < deg) ? __expf(e0 - m0) : 0.f;
        float ee1 = (lane < deg) ? __expf(e1 - m1) : 0.f;
        float s0 = ee0, s1 = ee1;
#pragma unroll
        for (int o = 16; o; o >>= 1) {
            s0 += __shfl_xor_sync(FULL, s0, o);
            s1 += __shfl_xor_sync(FULL, s1, o);
        }
        float al0 = ee0 / (s0 + 1e-16f);
        float al1 = ee1 / (s1 + 1e-16f);

        int i = 0;
        for (; i + 2 <= deg; i += 2) {
            int sa = __shfl_sync(FULL, s, i);
            int sb = __shfl_sync(FULL, s, i + 1);
            float a0a = __shfl_sync(FULL, al0, i);
            float a1a = __shfl_sync(FULL, al1, i);
            float a0b = __shfl_sync(FULL, al0, i + 1);
            float a1b = __shfl_sync(FULL, al1, i + 1);
            float aa = h ? a1a : a0a;
            float ab = h ? a1b : a0b;
            float4 va = load_h4(sa, lane);
            float4 vb = load_h4(sb, lane);
            acc.x = fmaf(aa, va.x, fmaf(ab, vb.x, acc.x));
            acc.y = fmaf(aa, va.y, fmaf(ab, vb.y, acc.y));
            acc.z = fmaf(aa, va.z, fmaf(ab, vb.z, acc.z));
            acc.w = fmaf(aa, va.w, fmaf(ab, vb.w, acc.w));
        }
        if (i < deg) {
            int sa = __shfl_sync(FULL, s, i);
            float a0a = __shfl_sync(FULL, al0, i);
            float a1a = __shfl_sync(FULL, al1, i);
            float aa = h ? a1a : a0a;
            float4 va = load_h4(sa, lane);
            acc.x = fmaf(aa, va.x, acc.x);
            acc.y = fmaf(aa, va.y, acc.y);
            acc.z = fmaf(aa, va.z, acc.z);
            acc.w = fmaf(aa, va.w, acc.w);
        }
    } else {
        float m0 = -1e30f, m1 = -1e30f;
        for (int i = beg + lane; i < end; i += 32) {
            int s = g_srt[i];
            m0 = fmaxf(m0, lrelu(g_as[s * 2]     + ad0));
            m1 = fmaxf(m1, lrelu(g_as[s * 2 + 1] + ad1));
        }
#pragma unroll
        for (int o = 16; o; o >>= 1) {
            m0 = fmaxf(m0, __shfl_xor_sync(FULL, m0, o));
            m1 = fmaxf(m1, __shfl_xor_sync(FULL, m1, o));
        }
        float s0 = 0.f, s1 = 0.f;
        for (int i = beg + lane; i < end; i += 32) {
            int s = g_srt[i];
            s0 += __expf(lrelu(g_as[s * 2]     + ad0) - m0);
            s1 += __expf(lrelu(g_as[s * 2 + 1] + ad1) - m1);
        }
#pragma unroll
        for (int o = 16; o; o >>= 1) {
            s0 += __shfl_xor_sync(FULL, s0, o);
            s1 += __shfl_xor_sync(FULL, s1, o);
        }
        float mh  = h ? m1 : m0;
        float adh = h ? ad1 : ad0;
        float inv = 1.f / ((h ? s1 : s0) + 1e-16f);
        for (int i = beg; i < end; i++) {
            int s = g_srt[i];
            float a = __expf(lrelu(g_as[s * 2 + h] + adh) - mh) * inv;
            float4 hv = load_h4(s, lane);
            acc.x = fmaf(a, hv.x, acc.x);
            acc.y = fmaf(a, hv.y, acc.y);
            acc.z = fmaf(a, hv.z, acc.z);
            acc.w = fmaf(a, hv.w, acc.w);
        }
    }

    float ox = __shfl_down_sync(FULL, acc.x, 16);
    float oy = __shfl_down_sync(FULL, acc.y, 16);
    float oz = __shfl_down_sync(FULL, acc.z, 16);
    float ow = __shfl_down_sync(FULL, acc.w, 16);
    if (lane < 16) {
        const float4 b4 = ((const float4*)bias)[lane];
        float4 r;
        r.x = 0.5f * (acc.x + ox) + b4.x;
        r.y = 0.5f * (acc.y + oy) + b4.y;
        r.z = 0.5f * (acc.z + oz) + b4.z;
        r.w = 0.5f * (acc.w + ow) + b4.w;
        ((float4*)g_hm)[node * 16 + lane] = r;
    }
}

// ==================== BN stats + fused finalize (last-block) ====================
__global__ void bn_stats_kernel(const float* __restrict__ gw, const float* __restrict__ be, int layer) {
    int c4 = threadIdx.x & 15;
    int r  = threadIdx.x >> 4;
    float4 s1 = make_float4(0.f, 0.f, 0.f, 0.f);
    float4 s2 = make_float4(0.f, 0.f, 0.f, 0.f);
    for (int n = blockIdx.x * 16 + r; n < NN; n += gridDim.x * 16) {
        float4 v = ((const float4*)g_hm)[n * 16 + c4];
        s1.x += v.x; s1.y += v.y; s1.z += v.z; s1.w += v.w;
        s2.x = fmaf(v.x, v.x, s2.x); s2.y = fmaf(v.y, v.y, s2.y);
        s2.z = fmaf(v.z, v.z, s2.z); s2.w = fmaf(v.w, v.w, s2.w);
    }
    __shared__ float4 sh1[256], sh2[256];
    sh1[threadIdx.x] = s1; sh2[threadIdx.x] = s2;
    __syncthreads();
    for (int o = 8; o; o >>= 1) {
        if (r < o) {
            float4 a = sh1[threadIdx.x + o * 16], b = sh2[threadIdx.x + o * 16];
            s1.x += a.x; s1.y += a.y; s1.z += a.z; s1.w += a.w;
            s2.x += b.x; s2.y += b.y; s2.z += b.z; s2.w += b.w;
            sh1[threadIdx.x] = s1; sh2[threadIdx.x] = s2;
        }
        __syncthreads();
    }
    if (r == 0) {
        int c = c4 * 4;
        atomicAdd(&g_cs[layer][c + 0], (double)s1.x);
        atomicAdd(&g_cs[layer][c + 1], (double)s1.y);
        atomicAdd(&g_cs[layer][c + 2], (double)s1.z);
        atomicAdd(&g_cs[layer][c + 3], (double)s1.w);
        atomicAdd(&g_css[layer][c + 0], (double)s2.x);
        atomicAdd(&g_css[layer][c + 1], (double)s2.y);
        atomicAdd(&g_css[layer][c + 2], (double)s2.z);
        atomicAdd(&g_css[layer][c + 3], (double)s2.w);
        __threadfence();
    }
    __syncthreads();
    __shared__ int lastf;
    if (threadIdx.x == 0) lastf = (atomicAdd(&g_done, 1) == (int)gridDim.x - 1) ? 1 : 0;
    __syncthreads();
    if (lastf) {
        if (threadIdx.x == 0) g_done = 0;
        if (threadIdx.x < CC) {
            int c = threadIdx.x;
            float m = (float)(g_cs[layer][c] / (double)NN);
            float var = (float)(g_css[layer][c] / (double)NN) - m * m;
            var = fmaxf(var, 0.f);
            float sc = rsqrtf(var + EPS) * gw[c];
            g_scale[c] = sc;
            g_shift[c] = be[c] - m * sc;
        }
    }
}

// ==================== MLP v2: one node per thread, smem weights broadcast ====================
__global__ void __launch_bounds__(128) mlp2_kernel(const float* __restrict__ x0,
                           const float* __restrict__ mW1, const float* __restrict__ mb1,
                           const float* __restrict__ mW2, const float* __restrict__ mb2,
                           const float* __restrict__ pW, const float* __restrict__ pb,
                           const float* __restrict__ vW, const float* __restrict__ vb,
                           float* __restrict__ out) {
    __shared__ __align__(16) float m1t[64][72];   // m1t[j][k] = mW1[k*64+j], k<69, pad 0
    __shared__ __align__(16) float m2t[64][64];   // m2t[j][k] = mW2[k*64+j]
    __shared__ float mb1s[64], mb2s[64], pWs[64], vWs[64];
    int tid = threadIdx.x;
    for (int i = tid; i < 64 * 72; i += 128) ((float*)m1t)[i] = 0.f;
    __syncthreads();
    for (int i = tid; i < 69 * 64; i += 128) { int k = i >> 6, j = i & 63; m1t[j][k] = mW1[i]; }
    for (int i = tid; i < 64 * 64; i += 128) { int k = i >> 6, j = i & 63; m2t[j][k] = mW2[i]; }
    if (tid < 64) { mb1s[tid] = mb1[tid]; mb2s[tid] = mb2[tid]; pWs[tid] = pW[tid]; vWs[tid] = vW[tid]; }
    __syncthreads();

    int n = blockIdx.x * 128 + tid;
    if (n >= NN) return;

    float4 hc4[18];
#pragma unroll
    for (int k4 = 0; k4 < 16; k4++) {
        float4 v = ((const float4*)g_hm)[n * 16 + k4];
        float4 sc = ((const float4*)g_scale)[k4];
        float4 sh = ((const float4*)g_shift)[k4];
        v.x = fmaxf(fmaf(v.x, sc.x, sh.x), 0.f);
        v.y = fmaxf(fmaf(v.y, sc.y, sh.y), 0.f);
        v.z = fmaxf(fmaf(v.z, sc.z, sh.z), 0.f);
        v.w = fmaxf(fmaf(v.w, sc.w, sh.w), 0.f);
        hc4[k4] = v;
    }
    hc4[16] = make_float4(x0[n * 16 + 9], x0[n * 16 + 10], x0[n * 16 + 11], x0[n * 16 + 12]);
    hc4[17] = make_float4(x0[n * 16 + 13], 0.f, 0.f, 0.f);

    float h1[64];
#pragma unroll
    for (int j = 0; j < 64; j++) {
        float a = mb1s[j];
#pragma unroll
        for (int k4 = 0; k4 < 18; k4++) {
            float4 w = ((const float4*)m1t[j])[k4];
            a = fmaf(hc4[k4].x, w.x, a);
            a = fmaf(hc4[k4].y, w.y, a);
            a = fmaf(hc4[k4].z, w.z, a);
            a = fmaf(hc4[k4].w, w.w, a);
        }
        h1[j] = fmaxf(a, 0.f);
    }
    float lg = 0.f, vl = 0.f;
#pragma unroll
    for (int j = 0; j < 64; j++) {
        float b = mb2s[j];
#pragma unroll
        for (int k4 = 0; k4 < 16; k4++) {
            float4 w = ((const float4*)m2t[j])[k4];
            b = fmaf(h1[k4 * 4 + 0], w.x, b);
            b = fmaf(h1[k4 * 4 + 1], w.y, b);
            b = fmaf(h1[k4 * 4 + 2], w.z, b);
            b = fmaf(h1[k4 * 4 + 3], w.w, b);
        }
        lg = fmaf(b, pWs[j], lg);
        vl = fmaf(b, vWs[j], vl);
    }
    out[n]      = lg + pb[0];
    out[NN + n] = vl + vb[0];
}

// ==================== launch ====================
extern "C" void kernel_launch(void* const* d_in, const int* in_sizes, int n_in,
                              void* d_out, int out_size) {
    const float* x   = (const float*)d_in[0];
    const int*   ei  = (const int*)d_in[1];
    const int*   src = ei;
    const int*   dst = ei + EE;
    float* out = (float*)d_out;

    // ---- CSR build ----
    init_kernel<<<(NN + 255) / 256, 256>>>();
    int eb = (ET + 255) / 256;
    hist_kernel<<<eb, 256>>>(dst);
    scan1_kernel<<<NB1, 1024>>>();
    scan2_kernel<<<1, 128>>>();
    scan3_kernel<<<(NN + 255) / 256, 256>>>();
    scatter_kernel<<<eb, 256>>>(src, dst);

    const int base[3] = {2, 8, 14};

    for (int l = 0; l < 3; l++) {
        const float* W   = (const float*)d_in[base[l] + 0];
        const float* as_ = (const float*)d_in[base[l] + 1];
        const float* ad_ = (const float*)d_in[base[l] + 2];
        const float* b_  = (const float*)d_in[base[l] + 3];
        const float* g_  = (const float*)d_in[base[l] + 4];
        const float* be_ = (const float*)d_in[base[l] + 5];

        if (l == 0) lin2_kernel<16, false><<<1184, 128>>>(x, W, as_, ad_);
        else        lin2_kernel<64, true ><<<1184, 128>>>(x, W, as_, ad_);
        agg_kernel<<<(NN + 7) / 8, 256>>>(b_);
        bn_stats_kernel<<<296, 256>>>(g_, be_, l);
    }

    const float* mW1 = (const float*)d_in[20];
    const float* mb1 = (const float*)d_in[21];
    const float* mW2 = (const float*)d_in[22];
    const float* mb2 = (const float*)d_in[23];
    const float* pW  = (const float*)d_in[24];
    const float* pb  = (const float*)d_in[25];
    const float* vW  = (const float*)d_in[26];
    const float* vb  = (const float*)d_in[27];
    mlp2_kernel<<<(NN + 127) / 128, 128>>>(x, mW1, mb1, mW2, mb2, pW, pb, vW, vb, out);
}